// round 15
// baseline (speedup 1.0000x reference)
#include <cuda_runtime.h>

// QuantBatchedEmbeddingBag: T=8 tables, R=200000 rows, D=128, B=2048 bags/table.
// Inputs (metadata order):
//   d_in[0] indices     int32 [N = 524288]
//   d_in[1] offsets     int32 [T*B + 1 = 16385]  (CSR bag boundaries, feature-major)
//   d_in[2] qweights    int32 [T, R, D]          (int8 codes in [0,256) stored as int32)
//   d_in[3] scale_shift float32 [T, R, 2]
// Output: float32 [B, T*D] = [2048, 1024], out[b, t*D + d] = pooled[t*B + b, d]

#define T_TABLES 8
#define R_ROWS   200000
#define D_DIM    128
#define B_BATCH  2048
#define NUM_BAGS (T_TABLES * B_BATCH)
#define PIPE     6   // gather pipeline depth (R9-proven)
#define WPB      4   // warps cooperating per bag
#define BPC      2   // bags per CTA: idx latencies of both bags overlap

__global__ __launch_bounds__(WPB * 32, 10)   // <=51 regs -> 10 CTAs/SM = 40 warps
void embbag_kernel(const int*   __restrict__ indices,
                   const int*   __restrict__ offsets,
                   const int*   __restrict__ qweights,
                   const float* __restrict__ scale_shift,
                   float*       __restrict__ out)
{
    const int bag0 = blockIdx.x * BPC;     // pair of consecutive bags, same table
    const int s    = threadIdx.x >> 5;     // sub-warp id within bag (0..3)
    const int lane = threadIdx.x & 31;

    const int t  = bag0 / B_BATCH;         // table (B_BATCH even -> pair never straddles)
    const int b0 = bag0 % B_BATCH;

    const int4*   qbase  = reinterpret_cast<const int4*>(
                               qweights + (long long)t * R_ROWS * D_DIM);
    const float2* ssbase = reinterpret_cast<const float2*>(scale_shift)
                               + (long long)t * R_ROWS;

    // Bag extents (3 offsets cover both bags).
    const int o0 = offsets[bag0];
    const int o1 = offsets[bag0 + 1];
    const int o2 = offsets[bag0 + 2];

    const int cnt0 = (o1 - o0 > s) ? (o1 - o0 - s + WPB - 1) / WPB : 0;
    const int cnt1 = (o2 - o1 > s) ? (o2 - o1 - s + WPB - 1) / WPB : 0;

    // Issue BOTH bags' first index chunk-loads back-to-back: their ~600cyc
    // latencies overlap -> one idx bubble per two bags instead of per bag.
    int pidx0 = (lane < cnt0) ? __ldg(indices + o0 + s + WPB * lane) : 0;
    int pidx1 = (lane < cnt1) ? __ldg(indices + o1 + s + WPB * lane) : 0;

    __shared__ float4 red[BPC][WPB][32];

    #pragma unroll
    for (int bi = 0; bi < BPC; bi++) {
        const int start = (bi == 0) ? o0 : o1;
        const int count = (bi == 0) ? cnt0 : cnt1;
        int       myidx = (bi == 0) ? pidx0 : pidx1;   // prefetched chunk 0

        float4 acc = make_float4(0.f, 0.f, 0.f, 0.f);
        float  shift_sum = 0.f;

        for (int jbase = 0; jbase < count; jbase += 32) {
            const int n = min(32, count - jbase);      // valid lanes are a prefix
            if (jbase > 0) {                           // rare tail chunks (len>128)
                const int  j = jbase + lane;
                myidx = (j < count) ? __ldg(indices + start + s + WPB * j) : 0;
            }

            // Scale/shift gather (for bag1 this issues AFTER bag0's rows, by
            // which time pidx1 has long since landed -> no stall here).
            float2 myss = make_float2(0.f, 0.f);
            if (jbase + lane < count) myss = __ldg(ssbase + myidx);

            // Row gather in groups of PIPE, R9-proven interleaved form.
            for (int g = 0; g < n; g += PIPE) {
                const int m = min(PIPE, n - g);
                int4 q[PIPE];
                #pragma unroll
                for (int k = 0; k < PIPE; k++) {
                    if (k < m) {
                        const int row = __shfl_sync(0xffffffffu, myidx, g + k);
                        q[k] = __ldg(qbase + (long long)row * (D_DIM / 4) + lane);
                    }
                }
                #pragma unroll
                for (int k = 0; k < PIPE; k++) {
                    if (k < m) {
                        const float sc = __shfl_sync(0xffffffffu, myss.x, g + k);
                        acc.x = fmaf((float)q[k].x, sc, acc.x);
                        acc.y = fmaf((float)q[k].y, sc, acc.y);
                        acc.z = fmaf((float)q[k].z, sc, acc.z);
                        acc.w = fmaf((float)q[k].w, sc, acc.w);
                    }
                }
            }

            // Warp-reduce the shifts once per chunk (invalid lanes hold 0).
            float sh = myss.y;
            #pragma unroll
            for (int d = 16; d > 0; d >>= 1)
                sh += __shfl_xor_sync(0xffffffffu, sh, d);
            shift_sum += sh;
        }

        acc.x += shift_sum;
        acc.y += shift_sum;
        acc.z += shift_sum;
        acc.w += shift_sum;

        // Park partials in smem immediately (no sync here: sub-warps stay
        // decoupled, and acc registers free up for the next bag).
        red[bi][s][lane] = acc;
    }

    // Single end-of-CTA barrier, then combine + store both bags.
    __syncthreads();
    if (s < BPC) {            // sub-warp s reduces bag s
        float4 a0 = red[s][0][lane];
        float4 a1 = red[s][1][lane];
        float4 a2 = red[s][2][lane];
        float4 a3 = red[s][3][lane];
        a0.x += a1.x + a2.x + a3.x;
        a0.y += a1.y + a2.y + a3.y;
        a0.z += a1.z + a2.z + a3.z;
        a0.w += a1.w + a2.w + a3.w;
        // out[b, t*D + lane*4 .. +3] -> float4 element index (b*T + t)*32 + lane
        reinterpret_cast<float4*>(out)[
            ((long long)(b0 + s) * T_TABLES + t) * (D_DIM / 4) + lane] = a0;
    }
}

extern "C" void kernel_launch(void* const* d_in, const int* in_sizes, int n_in,
                              void* d_out, int out_size)
{
    const int*   indices     = (const int*)  d_in[0];
    const int*   offsets     = (const int*)  d_in[1];
    const int*   qweights    = (const int*)  d_in[2];
    const float* scale_shift = (const float*)d_in[3];
    float*       out         = (float*)      d_out;

    embbag_kernel<<<NUM_BAGS / BPC, WPB * 32>>>(indices, offsets, qweights,
                                                scale_shift, out);
}